// round 11
// baseline (speedup 1.0000x reference)
#include <cuda_runtime.h>
#include <cuda_fp16.h>
#include <cstdint>
#include <cstddef>

#define DIMD   1024
#define TT     8192     // B*N = B*M rows
#define HD     64       // head dim
#define SEQ    2048

// ---------------- scratch ----------------
__device__ float  g_Qp [TT * DIMD];   // fp32 Q projection (residual)
__device__ float  g_Oh [TT * DIMD];   // fp32 attention out (residual for final gemm)
__device__ __half g_Qh [TT * DIMD];
__device__ __half g_Kh [TT * DIMD];
__device__ __half g_Vh [TT * DIMD];
__device__ __half g_OhH[TT * DIMD];
__device__ __half g_Xq [TT * DIMD];   // fp16 input Q
__device__ __half g_Xk [TT * DIMD];   // fp16 input K
__device__ __half g_Wq [DIMD * DIMD];
__device__ __half g_Wk [DIMD * DIMD];
__device__ __half g_Wv [DIMD * DIMD];
__device__ __half g_Wo [DIMD * DIMD];

// =========================== helpers =================================
__device__ __forceinline__ uint32_t smem_u32(const void* p) {
    uint32_t a;
    asm("{ .reg .u64 t; cvta.to.shared.u64 t, %1; cvt.u32.u64 %0, t; }"
        : "=r"(a) : "l"(p));
    return a;
}

#define LDSM_X4(R0, R1, R2, R3, addr) \
    asm volatile("ldmatrix.sync.aligned.m8n8.x4.shared.b16 {%0,%1,%2,%3}, [%4];" \
                 : "=r"(R0), "=r"(R1), "=r"(R2), "=r"(R3) : "r"(addr))

#define LDSM_X4_T(R0, R1, R2, R3, addr) \
    asm volatile("ldmatrix.sync.aligned.m8n8.x4.trans.shared.b16 {%0,%1,%2,%3}, [%4];" \
                 : "=r"(R0), "=r"(R1), "=r"(R2), "=r"(R3) : "r"(addr))

#define MMA_F16(c, a, b0, b1) \
    asm volatile("mma.sync.aligned.m16n8k16.row.col.f32.f16.f16.f32 " \
                 "{%0,%1,%2,%3}, {%4,%5,%6,%7}, {%8,%9}, {%0,%1,%2,%3};" \
                 : "+f"((c)[0]), "+f"((c)[1]), "+f"((c)[2]), "+f"((c)[3]) \
                 : "r"((a)[0]), "r"((a)[1]), "r"((a)[2]), "r"((a)[3]), \
                   "r"(b0), "r"(b1))

__device__ __forceinline__ uint32_t pkhf(float lo, float hi) {
    uint32_t d;
    asm("cvt.rn.f16x2.f32 %0, %1, %2;" : "=r"(d) : "f"(hi), "f"(lo));
    return d;
}

// swizzled smem address: 128B rows, 8 chunks of 16B, chunk c XOR (r&7)
__device__ __forceinline__ uint32_t sw_addr(uint32_t base, int r, int c) {
    return base + (uint32_t)(r * 128) + (uint32_t)(((c ^ (r & 7)) & 7) << 4);
}

__device__ __forceinline__ void st16(uint32_t a, uint4 v) {
    asm volatile("st.shared.v4.b32 [%0], {%1,%2,%3,%4};"
                 :: "r"(a), "r"(v.x), "r"(v.y), "r"(v.z), "r"(v.w));
}

// ================================================================================
// fp32 -> fp16 conversion (elementwise, 8 per thread)
// ================================================================================
__global__ void __launch_bounds__(256)
f2h_kernel(const float* __restrict__ in, __half* __restrict__ out, int n)
{
    int i = (blockIdx.x * 256 + threadIdx.x) * 8;
    if (i >= n) return;
    float4 a = *(const float4*)(in + i);
    float4 b = *(const float4*)(in + i + 4);
    uint4 o;
    o.x = pkhf(a.x, a.y); o.y = pkhf(a.z, a.w);
    o.z = pkhf(b.x, b.y); o.w = pkhf(b.z, b.w);
    *(uint4*)(out + i) = o;
}

// ================================================================================
// All-fp16-operand GEMM: C = Xh[8192,1024] @ Wh^T + bias
//   MODE 0: fp16 CH only      MODE 1: fp16 CH + fp32 C32
//   MODE 2: fp32 C = R + relu(acc + bias)
// 128x128 tile, BK=32, 256 threads (8 warps, 2m x 4n), warp tile 64x32.
// ================================================================================
#define GEMM_SMEM (2 * 32768)

template <int MODE>
__global__ void __launch_bounds__(256)
gemm_h(const __half* __restrict__ X, const __half* __restrict__ W,
       const float* __restrict__ bias, const float* __restrict__ R,
       float* __restrict__ C32, __half* __restrict__ CH)
{
    extern __shared__ char sm[];
    const uint32_t sb = smem_u32(sm);

    const int t    = threadIdx.x;
    const int w    = t >> 5;
    const int lane = t & 31;
    const int wm   = w >> 2;
    const int wn   = w & 3;
    const int bn   = blockIdx.x;
    const int bm   = blockIdx.y;

    float acc[4][4][4];
    #pragma unroll
    for (int mi = 0; mi < 4; mi++)
        #pragma unroll
        for (int ni = 0; ni < 4; ni++)
            #pragma unroll
            for (int q = 0; q < 4; q++) acc[mi][ni][q] = 0.0f;

    const int r_ = t >> 1;          // staging row 0..127
    const int s0 = (t & 1) * 2;     // first of 2 chunk-pairs

    uint4 stA[2], stB[2];
    {
        const __half* pA = X + (size_t)(bm * 128 + r_) * DIMD + s0 * 8;
        const __half* pB = W + (size_t)(bn * 128 + r_) * DIMD + s0 * 8;
        stA[0] = *(const uint4*)(pA);     stA[1] = *(const uint4*)(pA + 8);
        stB[0] = *(const uint4*)(pB);     stB[1] = *(const uint4*)(pB + 8);
    }

    const int rin = lane & 15;
    const int hb  = lane >> 4;

    for (int ch = 0; ch < 32; ch++) {
        const uint32_t Ab = sb + (uint32_t)(ch & 1) * 32768u;
        const uint32_t Bb = Ab + 16384u;

        st16(sw_addr(Ab, r_, s0),     stA[0]);
        st16(sw_addr(Ab, r_, s0 + 1), stA[1]);
        st16(sw_addr(Bb, r_, s0),     stB[0]);
        st16(sw_addr(Bb, r_, s0 + 1), stB[1]);
        __syncthreads();

        if (ch + 1 < 32) {
            const int k0 = (ch + 1) * 32;
            const __half* pA = X + (size_t)(bm * 128 + r_) * DIMD + k0 + s0 * 8;
            const __half* pB = W + (size_t)(bn * 128 + r_) * DIMD + k0 + s0 * 8;
            stA[0] = *(const uint4*)(pA);     stA[1] = *(const uint4*)(pA + 8);
            stB[0] = *(const uint4*)(pB);     stB[1] = *(const uint4*)(pB + 8);
        }

        #pragma unroll
        for (int ks = 0; ks < 2; ks++) {
            const int chi = ks * 2 + hb;
            uint32_t afr[4][4];
            #pragma unroll
            for (int mi = 0; mi < 4; mi++)
                LDSM_X4(afr[mi][0], afr[mi][1], afr[mi][2], afr[mi][3],
                        sw_addr(Ab, wm * 64 + mi * 16 + rin, chi));
            uint32_t bh[2][4];
            #pragma unroll
            for (int pi = 0; pi < 2; pi++)
                LDSM_X4(bh[pi][0], bh[pi][1], bh[pi][2], bh[pi][3],
                        sw_addr(Bb, wn * 32 + pi * 16 + rin, chi));
            #pragma unroll
            for (int mi = 0; mi < 4; mi++)
                #pragma unroll
                for (int ni = 0; ni < 4; ni++)
                    MMA_F16(acc[mi][ni], afr[mi],
                            bh[ni >> 1][ni & 1], bh[ni >> 1][(ni & 1) + 2]);
        }
        __syncthreads();
    }

    const int rbase = bm * 128 + wm * 64;
    const int cbase = bn * 128 + wn * 32;
    float bb[4][2];
    #pragma unroll
    for (int ni = 0; ni < 4; ni++) {
        int c0 = cbase + ni * 8 + (lane & 3) * 2;
        bb[ni][0] = bias[c0];
        bb[ni][1] = bias[c0 + 1];
    }

    #pragma unroll
    for (int mi = 0; mi < 4; mi++) {
        #pragma unroll
        for (int ni = 0; ni < 4; ni++) {
            int r0 = rbase + mi * 16 + (lane >> 2);
            int c0 = cbase + ni * 8 + (lane & 3) * 2;
            float o0 = acc[mi][ni][0] + bb[ni][0];
            float o1 = acc[mi][ni][1] + bb[ni][1];
            float o2 = acc[mi][ni][2] + bb[ni][0];
            float o3 = acc[mi][ni][3] + bb[ni][1];
            if (MODE == 2) {
                float2 ra = *(const float2*)&R[(size_t)r0 * DIMD + c0];
                float2 rb = *(const float2*)&R[(size_t)(r0 + 8) * DIMD + c0];
                o0 = fmaxf(o0, 0.0f) + ra.x;
                o1 = fmaxf(o1, 0.0f) + ra.y;
                o2 = fmaxf(o2, 0.0f) + rb.x;
                o3 = fmaxf(o3, 0.0f) + rb.y;
                *(float2*)&C32[(size_t)r0 * DIMD + c0]       = make_float2(o0, o1);
                *(float2*)&C32[(size_t)(r0 + 8) * DIMD + c0] = make_float2(o2, o3);
            } else {
                *(uint32_t*)&CH[(size_t)r0 * DIMD + c0]       = pkhf(o0, o1);
                *(uint32_t*)&CH[(size_t)(r0 + 8) * DIMD + c0] = pkhf(o2, o3);
                if (MODE == 1) {
                    *(float2*)&C32[(size_t)r0 * DIMD + c0]       = make_float2(o0, o1);
                    *(float2*)&C32[(size_t)(r0 + 8) * DIMD + c0] = make_float2(o2, o3);
                }
            }
        }
    }
}

// ================================================================================
// Tensor-core flash attention per (b,h): Br=256 (CTA), Bc=64, d=64, 8 warps.
// Each warp owns 32 Q rows (2 m-tiles) -> halves LDSM traffic per MMA.
// fp16 inputs, fp32 accum. No max subtraction (scores provably tiny).
// ================================================================================
#define ATT_SMEM (32768 + 8192 + 8192)

__global__ void __launch_bounds__(256, 1)
attn_mma(const __half* __restrict__ Qh, const __half* __restrict__ Kh,
         const __half* __restrict__ Vh, const float* __restrict__ Qp,
         float* __restrict__ Oh, __half* __restrict__ OhH)
{
    extern __shared__ char smatt[];
    const uint32_t sb = smem_u32(smatt);
    const uint32_t Qs = sb;
    const uint32_t Ks = sb + 32768;
    const uint32_t Vs = sb + 40960;

    const int t    = threadIdx.x;
    const int w    = t >> 5;
    const int lane = t & 31;
    const int rin  = lane & 15;
    const int hb   = lane >> 4;
    const int bh   = blockIdx.y;
    const int b    = bh >> 4;
    const int h    = bh & 15;
    const int n0   = blockIdx.x * 256;

    const size_t base = (size_t)b * SEQ * DIMD + (size_t)h * HD;

    // ---- stage Q tile: 256 rows x 64 d fp16, swizzled (1 row per thread,
    //      ALL 8 16B-chunks of the 128B row) ----
    {
        const __half* src = Qh + base + (size_t)(n0 + t) * DIMD;
        #pragma unroll
        for (int g = 0; g < 8; g++)
            st16(sw_addr(Qs, t, g), *(const uint4*)(src + g * 8));
    }
    __syncthreads();

    // ---- load Q fragments once: 2 m-tiles x 4 k-steps ----
    uint32_t qf[2][4][4];
    #pragma unroll
    for (int mi = 0; mi < 2; mi++)
        #pragma unroll
        for (int ks = 0; ks < 4; ks++)
            LDSM_X4(qf[mi][ks][0], qf[mi][ks][1], qf[mi][ks][2], qf[mi][ks][3],
                    sw_addr(Qs, w * 32 + mi * 16 + rin, 2 * ks + hb));

    float oacc[2][8][4];
    #pragma unroll
    for (int mi = 0; mi < 2; mi++)
        #pragma unroll
        for (int j = 0; j < 8; j++)
            #pragma unroll
            for (int q = 0; q < 4; q++) oacc[mi][j][q] = 0.0f;
    float lr[2][2] = {{0.0f, 0.0f}, {0.0f, 0.0f}};

    // prefetch chunk 0 (K and V, 32B each per thread)
    const int srow = t >> 2;
    const int sseg = t & 3;
    uint4 kpre[2], vpre[2];
    {
        const __half* kp = Kh + base + (size_t)srow * DIMD + sseg * 16;
        const __half* vp = Vh + base + (size_t)srow * DIMD + sseg * 16;
        kpre[0] = *(const uint4*)(kp);
        kpre[1] = *(const uint4*)(kp + 8);
        vpre[0] = *(const uint4*)(vp);
        vpre[1] = *(const uint4*)(vp + 8);
    }

    for (int m0 = 0; m0 < SEQ; m0 += 64) {
        st16(sw_addr(Ks, srow, sseg * 2),     kpre[0]);
        st16(sw_addr(Ks, srow, sseg * 2 + 1), kpre[1]);
        st16(sw_addr(Vs, srow, sseg * 2),     vpre[0]);
        st16(sw_addr(Vs, srow, sseg * 2 + 1), vpre[1]);
        __syncthreads();

        if (m0 + 64 < SEQ) {
            const __half* kp = Kh + base + (size_t)(m0 + 64 + srow) * DIMD + sseg * 16;
            const __half* vp = Vh + base + (size_t)(m0 + 64 + srow) * DIMD + sseg * 16;
            kpre[0] = *(const uint4*)(kp);
            kpre[1] = *(const uint4*)(kp + 8);
            vpre[0] = *(const uint4*)(vp);
            vpre[1] = *(const uint4*)(vp + 8);
        }

        // ---- S = Q K^T : 32 rows x 64 keys per warp ----
        float sacc[2][8][4];
        #pragma unroll
        for (int mi = 0; mi < 2; mi++)
            #pragma unroll
            for (int j = 0; j < 8; j++)
                #pragma unroll
                for (int q = 0; q < 4; q++) sacc[mi][j][q] = 0.0f;

        #pragma unroll
        for (int ks = 0; ks < 4; ks++) {
            uint32_t kb[4][4];
            #pragma unroll
            for (int pi = 0; pi < 4; pi++)
                LDSM_X4(kb[pi][0], kb[pi][1], kb[pi][2], kb[pi][3],
                        sw_addr(Ks, pi * 16 + rin, 2 * ks + hb));
            #pragma unroll
            for (int mi = 0; mi < 2; mi++)
                #pragma unroll
                for (int pi = 0; pi < 4; pi++) {
                    MMA_F16(sacc[mi][2 * pi],     qf[mi][ks], kb[pi][0], kb[pi][2]);
                    MMA_F16(sacc[mi][2 * pi + 1], qf[mi][ks], kb[pi][1], kb[pi][3]);
                }
        }

        // ---- p = exp(s/32); accumulate l; pack P ----
        uint32_t pf[2][8][2];
        #pragma unroll
        for (int mi = 0; mi < 2; mi++)
            #pragma unroll
            for (int j = 0; j < 8; j++) {
                float p0 = __expf(sacc[mi][j][0] * 0.03125f);
                float p1 = __expf(sacc[mi][j][1] * 0.03125f);
                float p2 = __expf(sacc[mi][j][2] * 0.03125f);
                float p3 = __expf(sacc[mi][j][3] * 0.03125f);
                lr[mi][0] += p0 + p1;
                lr[mi][1] += p2 + p3;
                pf[mi][j][0] = pkhf(p0, p1);
                pf[mi][j][1] = pkhf(p2, p3);
            }

        // ---- O += P @ V ----
        #pragma unroll
        for (int ks = 0; ks < 4; ks++) {
            uint32_t pa[2][4];
            #pragma unroll
            for (int mi = 0; mi < 2; mi++) {
                pa[mi][0] = pf[mi][2 * ks][0];     pa[mi][1] = pf[mi][2 * ks][1];
                pa[mi][2] = pf[mi][2 * ks + 1][0]; pa[mi][3] = pf[mi][2 * ks + 1][1];
            }
            #pragma unroll
            for (int pi = 0; pi < 4; pi++) {
                uint32_t vb0, vb1, vb2, vb3;
                LDSM_X4_T(vb0, vb1, vb2, vb3,
                          sw_addr(Vs, ks * 16 + rin, 2 * pi + hb));
                #pragma unroll
                for (int mi = 0; mi < 2; mi++) {
                    MMA_F16(oacc[mi][2 * pi],     pa[mi], vb0, vb1);
                    MMA_F16(oacc[mi][2 * pi + 1], pa[mi], vb2, vb3);
                }
            }
        }
        __syncthreads();
    }

    // ---- finalize: quad-reduce l, O = acc/l + Qp (fp32 residual) ----
    #pragma unroll
    for (int mi = 0; mi < 2; mi++) {
        lr[mi][0] += __shfl_xor_sync(0xffffffffu, lr[mi][0], 1);
        lr[mi][0] += __shfl_xor_sync(0xffffffffu, lr[mi][0], 2);
        lr[mi][1] += __shfl_xor_sync(0xffffffffu, lr[mi][1], 1);
        lr[mi][1] += __shfl_xor_sync(0xffffffffu, lr[mi][1], 2);
        const float inv0 = 1.0f / lr[mi][0];
        const float inv1 = 1.0f / lr[mi][1];

        const int r0 = n0 + w * 32 + mi * 16 + (lane >> 2);
        const int r1 = r0 + 8;
        #pragma unroll
        for (int j = 0; j < 8; j++) {
            const int col = j * 8 + (lane & 3) * 2;
            float2 q0 = *(const float2*)&Qp[base + (size_t)r0 * DIMD + col];
            float2 q1 = *(const float2*)&Qp[base + (size_t)r1 * DIMD + col];
            float o00 = oacc[mi][j][0] * inv0 + q0.x;
            float o01 = oacc[mi][j][1] * inv0 + q0.y;
            float o10 = oacc[mi][j][2] * inv1 + q1.x;
            float o11 = oacc[mi][j][3] * inv1 + q1.y;
            *(float2*)&Oh[base + (size_t)r0 * DIMD + col] = make_float2(o00, o01);
            *(float2*)&Oh[base + (size_t)r1 * DIMD + col] = make_float2(o10, o11);
            *(uint32_t*)&OhH[base + (size_t)r0 * DIMD + col] = pkhf(o00, o01);
            *(uint32_t*)&OhH[base + (size_t)r1 * DIMD + col] = pkhf(o10, o11);
        }
    }
}

// ================================================================================
extern "C" void kernel_launch(void* const* d_in, const int* in_sizes, int n_in,
                              void* d_out, int out_size)
{
    const float* Q  = (const float*)d_in[0];
    const float* K  = (const float*)d_in[1];
    const float* Wq = (const float*)d_in[2];
    const float* bq = (const float*)d_in[3];
    const float* Wk = (const float*)d_in[4];
    const float* bk = (const float*)d_in[5];
    const float* Wv = (const float*)d_in[6];
    const float* bv = (const float*)d_in[7];
    const float* Wo = (const float*)d_in[8];
    const float* bo = (const float*)d_in[9];
    float* out = (float*)d_out;

    float *Qp, *Oh;
    __half *Qh, *Kh, *Vh, *OhH, *Xq, *Xk, *WqH, *WkH, *WvH, *WoH;
    cudaGetSymbolAddress((void**)&Qp,  g_Qp);
    cudaGetSymbolAddress((void**)&Oh,  g_Oh);
    cudaGetSymbolAddress((void**)&Qh,  g_Qh);
    cudaGetSymbolAddress((void**)&Kh,  g_Kh);
    cudaGetSymbolAddress((void**)&Vh,  g_Vh);
    cudaGetSymbolAddress((void**)&OhH, g_OhH);
    cudaGetSymbolAddress((void**)&Xq,  g_Xq);
    cudaGetSymbolAddress((void**)&Xk,  g_Xk);
    cudaGetSymbolAddress((void**)&WqH, g_Wq);
    cudaGetSymbolAddress((void**)&WkH, g_Wk);
    cudaGetSymbolAddress((void**)&WvH, g_Wv);
    cudaGetSymbolAddress((void**)&WoH, g_Wo);

    cudaFuncSetAttribute(attn_mma,
                         cudaFuncAttributeMaxDynamicSharedMemorySize, ATT_SMEM);
    cudaFuncSetAttribute(gemm_h<0>,
                         cudaFuncAttributeMaxDynamicSharedMemorySize, GEMM_SMEM);
    cudaFuncSetAttribute(gemm_h<1>,
                         cudaFuncAttributeMaxDynamicSharedMemorySize, GEMM_SMEM);
    cudaFuncSetAttribute(gemm_h<2>,
                         cudaFuncAttributeMaxDynamicSharedMemorySize, GEMM_SMEM);

    // ---- pre-convert inputs + weights to fp16 (value-identical to in-loop cvt) ----
    const int nX = TT * DIMD, nW = DIMD * DIMD;
    f2h_kernel<<<nX / (256 * 8), 256>>>(Q,  Xq,  nX);
    f2h_kernel<<<nX / (256 * 8), 256>>>(K,  Xk,  nX);
    f2h_kernel<<<nW / (256 * 8), 256>>>(Wq, WqH, nW);
    f2h_kernel<<<nW / (256 * 8), 256>>>(Wk, WkH, nW);
    f2h_kernel<<<nW / (256 * 8), 256>>>(Wv, WvH, nW);
    f2h_kernel<<<nW / (256 * 8), 256>>>(Wo, WoH, nW);

    dim3 gg(8, 64);
    gemm_h<1><<<gg, 256, GEMM_SMEM>>>(Xq,  WqH, bq, nullptr, Qp, Qh);
    gemm_h<0><<<gg, 256, GEMM_SMEM>>>(Xk,  WkH, bk, nullptr, nullptr, Kh);
    gemm_h<0><<<gg, 256, GEMM_SMEM>>>(Xk,  WvH, bv, nullptr, nullptr, Vh);
    attn_mma<<<dim3(8, 64), 256, ATT_SMEM>>>(Qh, Kh, Vh, Qp, Oh, OhH);
    gemm_h<2><<<gg, 256, GEMM_SMEM>>>(OhH, WoH, bo, Oh, out, nullptr);
}

// round 12
// speedup vs baseline: 1.0390x; 1.0390x over previous
#include <cuda_runtime.h>
#include <cuda_fp16.h>
#include <cstdint>
#include <cstddef>

#define DIMD   1024
#define TT     8192     // B*N = B*M rows
#define HD     64       // head dim
#define SEQ    2048

// ---------------- scratch ----------------
__device__ float  g_Qp [TT * DIMD];   // fp32 Q projection (residual)
__device__ float  g_Oh [TT * DIMD];   // fp32 attention out (residual for final gemm)
__device__ __half g_Qh [TT * DIMD];
__device__ __half g_Kh [TT * DIMD];
__device__ __half g_Vh [TT * DIMD];
__device__ __half g_OhH[TT * DIMD];
__device__ __half g_Xq [TT * DIMD];   // fp16 input Q
__device__ __half g_Xk [TT * DIMD];   // fp16 input K
__device__ __half g_Wq [DIMD * DIMD];
__device__ __half g_Wk [DIMD * DIMD];
__device__ __half g_Wv [DIMD * DIMD];
__device__ __half g_Wo [DIMD * DIMD];

// =========================== helpers =================================
__device__ __forceinline__ uint32_t smem_u32(const void* p) {
    uint32_t a;
    asm("{ .reg .u64 t; cvta.to.shared.u64 t, %1; cvt.u32.u64 %0, t; }"
        : "=r"(a) : "l"(p));
    return a;
}

#define LDSM_X4(R0, R1, R2, R3, addr) \
    asm volatile("ldmatrix.sync.aligned.m8n8.x4.shared.b16 {%0,%1,%2,%3}, [%4];" \
                 : "=r"(R0), "=r"(R1), "=r"(R2), "=r"(R3) : "r"(addr))

#define LDSM_X4_T(R0, R1, R2, R3, addr) \
    asm volatile("ldmatrix.sync.aligned.m8n8.x4.trans.shared.b16 {%0,%1,%2,%3}, [%4];" \
                 : "=r"(R0), "=r"(R1), "=r"(R2), "=r"(R3) : "r"(addr))

#define MMA_F16(c, a, b0, b1) \
    asm volatile("mma.sync.aligned.m16n8k16.row.col.f32.f16.f16.f32 " \
                 "{%0,%1,%2,%3}, {%4,%5,%6,%7}, {%8,%9}, {%0,%1,%2,%3};" \
                 : "+f"((c)[0]), "+f"((c)[1]), "+f"((c)[2]), "+f"((c)[3]) \
                 : "r"((a)[0]), "r"((a)[1]), "r"((a)[2]), "r"((a)[3]), \
                   "r"(b0), "r"(b1))

__device__ __forceinline__ uint32_t pkhf(float lo, float hi) {
    uint32_t d;
    asm("cvt.rn.f16x2.f32 %0, %1, %2;" : "=r"(d) : "f"(hi), "f"(lo));
    return d;
}

// swizzled smem address: 128B rows, 8 chunks of 16B, chunk c XOR (r&7)
__device__ __forceinline__ uint32_t sw_addr(uint32_t base, int r, int c) {
    return base + (uint32_t)(r * 128) + (uint32_t)(((c ^ (r & 7)) & 7) << 4);
}

__device__ __forceinline__ void st16(uint32_t a, uint4 v) {
    asm volatile("st.shared.v4.b32 [%0], {%1,%2,%3,%4};"
                 :: "r"(a), "r"(v.x), "r"(v.y), "r"(v.z), "r"(v.w));
}

// ================================================================================
// fp32 -> fp16 conversion (elementwise, 8 per thread)
// ================================================================================
__global__ void __launch_bounds__(256)
f2h_kernel(const float* __restrict__ in, __half* __restrict__ out, int n)
{
    int i = (blockIdx.x * 256 + threadIdx.x) * 8;
    if (i >= n) return;
    float4 a = *(const float4*)(in + i);
    float4 b = *(const float4*)(in + i + 4);
    uint4 o;
    o.x = pkhf(a.x, a.y); o.y = pkhf(a.z, a.w);
    o.z = pkhf(b.x, b.y); o.w = pkhf(b.z, b.w);
    *(uint4*)(out + i) = o;
}

// ================================================================================
// All-fp16-operand GEMM: C = Xh[8192,1024] @ Wh^T + bias
//   MODE 0: fp16 CH only      MODE 1: fp16 CH + fp32 C32
//   MODE 2: fp32 C = R + relu(acc + bias)
// 128x128 tile, BK=32, 256 threads (8 warps, 2m x 4n), warp tile 64x32.
// ================================================================================
#define GEMM_SMEM (2 * 32768)

template <int MODE>
__global__ void __launch_bounds__(256)
gemm_h(const __half* __restrict__ X, const __half* __restrict__ W,
       const float* __restrict__ bias, const float* __restrict__ R,
       float* __restrict__ C32, __half* __restrict__ CH)
{
    extern __shared__ char sm[];
    const uint32_t sb = smem_u32(sm);

    const int t    = threadIdx.x;
    const int w    = t >> 5;
    const int lane = t & 31;
    const int wm   = w >> 2;
    const int wn   = w & 3;
    const int bn   = blockIdx.x;
    const int bm   = blockIdx.y;

    float acc[4][4][4];
    #pragma unroll
    for (int mi = 0; mi < 4; mi++)
        #pragma unroll
        for (int ni = 0; ni < 4; ni++)
            #pragma unroll
            for (int q = 0; q < 4; q++) acc[mi][ni][q] = 0.0f;

    const int r_ = t >> 1;          // staging row 0..127
    const int s0 = (t & 1) * 2;     // first of 2 chunk-pairs

    uint4 stA[2], stB[2];
    {
        const __half* pA = X + (size_t)(bm * 128 + r_) * DIMD + s0 * 8;
        const __half* pB = W + (size_t)(bn * 128 + r_) * DIMD + s0 * 8;
        stA[0] = *(const uint4*)(pA);     stA[1] = *(const uint4*)(pA + 8);
        stB[0] = *(const uint4*)(pB);     stB[1] = *(const uint4*)(pB + 8);
    }

    const int rin = lane & 15;
    const int hb  = lane >> 4;

    for (int ch = 0; ch < 32; ch++) {
        const uint32_t Ab = sb + (uint32_t)(ch & 1) * 32768u;
        const uint32_t Bb = Ab + 16384u;

        st16(sw_addr(Ab, r_, s0),     stA[0]);
        st16(sw_addr(Ab, r_, s0 + 1), stA[1]);
        st16(sw_addr(Bb, r_, s0),     stB[0]);
        st16(sw_addr(Bb, r_, s0 + 1), stB[1]);
        __syncthreads();

        if (ch + 1 < 32) {
            const int k0 = (ch + 1) * 32;
            const __half* pA = X + (size_t)(bm * 128 + r_) * DIMD + k0 + s0 * 8;
            const __half* pB = W + (size_t)(bn * 128 + r_) * DIMD + k0 + s0 * 8;
            stA[0] = *(const uint4*)(pA);     stA[1] = *(const uint4*)(pA + 8);
            stB[0] = *(const uint4*)(pB);     stB[1] = *(const uint4*)(pB + 8);
        }

        #pragma unroll
        for (int ks = 0; ks < 2; ks++) {
            const int chi = ks * 2 + hb;
            uint32_t afr[4][4];
            #pragma unroll
            for (int mi = 0; mi < 4; mi++)
                LDSM_X4(afr[mi][0], afr[mi][1], afr[mi][2], afr[mi][3],
                        sw_addr(Ab, wm * 64 + mi * 16 + rin, chi));
            uint32_t bh[2][4];
            #pragma unroll
            for (int pi = 0; pi < 2; pi++)
                LDSM_X4(bh[pi][0], bh[pi][1], bh[pi][2], bh[pi][3],
                        sw_addr(Bb, wn * 32 + pi * 16 + rin, chi));
            #pragma unroll
            for (int mi = 0; mi < 4; mi++)
                #pragma unroll
                for (int ni = 0; ni < 4; ni++)
                    MMA_F16(acc[mi][ni], afr[mi],
                            bh[ni >> 1][ni & 1], bh[ni >> 1][(ni & 1) + 2]);
        }
        __syncthreads();
    }

    const int rbase = bm * 128 + wm * 64;
    const int cbase = bn * 128 + wn * 32;
    float bb[4][2];
    #pragma unroll
    for (int ni = 0; ni < 4; ni++) {
        int c0 = cbase + ni * 8 + (lane & 3) * 2;
        bb[ni][0] = bias[c0];
        bb[ni][1] = bias[c0 + 1];
    }

    #pragma unroll
    for (int mi = 0; mi < 4; mi++) {
        #pragma unroll
        for (int ni = 0; ni < 4; ni++) {
            int r0 = rbase + mi * 16 + (lane >> 2);
            int c0 = cbase + ni * 8 + (lane & 3) * 2;
            float o0 = acc[mi][ni][0] + bb[ni][0];
            float o1 = acc[mi][ni][1] + bb[ni][1];
            float o2 = acc[mi][ni][2] + bb[ni][0];
            float o3 = acc[mi][ni][3] + bb[ni][1];
            if (MODE == 2) {
                float2 ra = *(const float2*)&R[(size_t)r0 * DIMD + c0];
                float2 rb = *(const float2*)&R[(size_t)(r0 + 8) * DIMD + c0];
                o0 = fmaxf(o0, 0.0f) + ra.x;
                o1 = fmaxf(o1, 0.0f) + ra.y;
                o2 = fmaxf(o2, 0.0f) + rb.x;
                o3 = fmaxf(o3, 0.0f) + rb.y;
                *(float2*)&C32[(size_t)r0 * DIMD + c0]       = make_float2(o0, o1);
                *(float2*)&C32[(size_t)(r0 + 8) * DIMD + c0] = make_float2(o2, o3);
            } else {
                *(uint32_t*)&CH[(size_t)r0 * DIMD + c0]       = pkhf(o0, o1);
                *(uint32_t*)&CH[(size_t)(r0 + 8) * DIMD + c0] = pkhf(o2, o3);
                if (MODE == 1) {
                    *(float2*)&C32[(size_t)r0 * DIMD + c0]       = make_float2(o0, o1);
                    *(float2*)&C32[(size_t)(r0 + 8) * DIMD + c0] = make_float2(o2, o3);
                }
            }
        }
    }
}

// ================================================================================
// Tensor-core flash attention per (b,h): Br=128 (CTA), Bc=64, d=64, 8 warps.
// (reverted to proven R9 config: 16 Q-rows/warp, 2 CTAs/SM, ~127 regs)
// fp16 inputs, fp32 accum. No max subtraction (scores provably tiny).
// ================================================================================
#define ATT_SMEM (16384 + 8192 + 8192)

__global__ void __launch_bounds__(256, 2)
attn_mma(const __half* __restrict__ Qh, const __half* __restrict__ Kh,
         const __half* __restrict__ Vh, const float* __restrict__ Qp,
         float* __restrict__ Oh, __half* __restrict__ OhH)
{
    extern __shared__ char smatt[];
    const uint32_t sb = smem_u32(smatt);
    const uint32_t Qs = sb;
    const uint32_t Ks = sb + 16384;
    const uint32_t Vs = sb + 24576;

    const int t    = threadIdx.x;
    const int w    = t >> 5;
    const int lane = t & 31;
    const int rin  = lane & 15;
    const int hb   = lane >> 4;
    const int bh   = blockIdx.y;
    const int b    = bh >> 4;
    const int h    = bh & 15;
    const int n0   = blockIdx.x * 128;

    const size_t base = (size_t)b * SEQ * DIMD + (size_t)h * HD;

    // ---- stage Q tile: 128 rows x 64 d fp16, swizzled ----
    {
        const int r  = t >> 1;
        const int c0 = (t & 1) * 4;           // 4 chunks of 16B
        const __half* src = Qh + base + (size_t)(n0 + r) * DIMD + c0 * 8;
        #pragma unroll
        for (int g = 0; g < 4; g++)
            st16(sw_addr(Qs, r, c0 + g), *(const uint4*)(src + g * 8));
    }
    __syncthreads();

    // ---- load Q fragments once ----
    uint32_t qf[4][4];
    #pragma unroll
    for (int ks = 0; ks < 4; ks++)
        LDSM_X4(qf[ks][0], qf[ks][1], qf[ks][2], qf[ks][3],
                sw_addr(Qs, w * 16 + rin, 2 * ks + hb));

    float oacc[8][4];
    #pragma unroll
    for (int j = 0; j < 8; j++)
        #pragma unroll
        for (int q = 0; q < 4; q++) oacc[j][q] = 0.0f;
    float l0 = 0.0f, l1 = 0.0f;

    // prefetch chunk 0 (K and V, 32B each per thread)
    const int srow = t >> 2;
    const int sseg = t & 3;
    uint4 kpre[2], vpre[2];
    {
        const __half* kp = Kh + base + (size_t)srow * DIMD + sseg * 16;
        const __half* vp = Vh + base + (size_t)srow * DIMD + sseg * 16;
        kpre[0] = *(const uint4*)(kp);
        kpre[1] = *(const uint4*)(kp + 8);
        vpre[0] = *(const uint4*)(vp);
        vpre[1] = *(const uint4*)(vp + 8);
    }

    for (int m0 = 0; m0 < SEQ; m0 += 64) {
        st16(sw_addr(Ks, srow, sseg * 2),     kpre[0]);
        st16(sw_addr(Ks, srow, sseg * 2 + 1), kpre[1]);
        st16(sw_addr(Vs, srow, sseg * 2),     vpre[0]);
        st16(sw_addr(Vs, srow, sseg * 2 + 1), vpre[1]);
        __syncthreads();

        if (m0 + 64 < SEQ) {
            const __half* kp = Kh + base + (size_t)(m0 + 64 + srow) * DIMD + sseg * 16;
            const __half* vp = Vh + base + (size_t)(m0 + 64 + srow) * DIMD + sseg * 16;
            kpre[0] = *(const uint4*)(kp);
            kpre[1] = *(const uint4*)(kp + 8);
            vpre[0] = *(const uint4*)(vp);
            vpre[1] = *(const uint4*)(vp + 8);
        }

        // ---- S = Q K^T ----
        float sacc[8][4];
        #pragma unroll
        for (int j = 0; j < 8; j++)
            #pragma unroll
            for (int q = 0; q < 4; q++) sacc[j][q] = 0.0f;

        #pragma unroll
        for (int ks = 0; ks < 4; ks++) {
            uint32_t kb[4][4];
            #pragma unroll
            for (int pi = 0; pi < 4; pi++)
                LDSM_X4(kb[pi][0], kb[pi][1], kb[pi][2], kb[pi][3],
                        sw_addr(Ks, pi * 16 + rin, 2 * ks + hb));
            #pragma unroll
            for (int pi = 0; pi < 4; pi++) {
                MMA_F16(sacc[2 * pi],     qf[ks], kb[pi][0], kb[pi][2]);
                MMA_F16(sacc[2 * pi + 1], qf[ks], kb[pi][1], kb[pi][3]);
            }
        }

        // ---- p = exp(s/32); accumulate l; pack P ----
        uint32_t pf[8][2];
        #pragma unroll
        for (int j = 0; j < 8; j++) {
            float p0 = __expf(sacc[j][0] * 0.03125f);
            float p1 = __expf(sacc[j][1] * 0.03125f);
            float p2 = __expf(sacc[j][2] * 0.03125f);
            float p3 = __expf(sacc[j][3] * 0.03125f);
            l0 += p0 + p1;
            l1 += p2 + p3;
            pf[j][0] = pkhf(p0, p1);
            pf[j][1] = pkhf(p2, p3);
        }

        // ---- O += P @ V  (V B-frags via ldmatrix.trans from row-major Vs) ----
        #pragma unroll
        for (int ks = 0; ks < 4; ks++) {
            uint32_t pa[4] = {pf[2 * ks][0], pf[2 * ks][1],
                              pf[2 * ks + 1][0], pf[2 * ks + 1][1]};
            #pragma unroll
            for (int pi = 0; pi < 4; pi++) {
                uint32_t vb0, vb1, vb2, vb3;
                LDSM_X4_T(vb0, vb1, vb2, vb3,
                          sw_addr(Vs, ks * 16 + rin, 2 * pi + hb));
                MMA_F16(oacc[2 * pi],     pa, vb0, vb1);
                MMA_F16(oacc[2 * pi + 1], pa, vb2, vb3);
            }
        }
        __syncthreads();
    }

    // ---- finalize: quad-reduce l, O = acc/l + Qp (fp32 residual) ----
    l0 += __shfl_xor_sync(0xffffffffu, l0, 1);
    l0 += __shfl_xor_sync(0xffffffffu, l0, 2);
    l1 += __shfl_xor_sync(0xffffffffu, l1, 1);
    l1 += __shfl_xor_sync(0xffffffffu, l1, 2);
    const float inv0 = 1.0f / l0;
    const float inv1 = 1.0f / l1;

    const int r0 = n0 + w * 16 + (lane >> 2);
    const int r1 = r0 + 8;
    #pragma unroll
    for (int j = 0; j < 8; j++) {
        const int col = j * 8 + (lane & 3) * 2;
        float2 q0 = *(const float2*)&Qp[base + (size_t)r0 * DIMD + col];
        float2 q1 = *(const float2*)&Qp[base + (size_t)r1 * DIMD + col];
        float o00 = oacc[j][0] * inv0 + q0.x;
        float o01 = oacc[j][1] * inv0 + q0.y;
        float o10 = oacc[j][2] * inv1 + q1.x;
        float o11 = oacc[j][3] * inv1 + q1.y;
        *(float2*)&Oh[base + (size_t)r0 * DIMD + col] = make_float2(o00, o01);
        *(float2*)&Oh[base + (size_t)r1 * DIMD + col] = make_float2(o10, o11);
        *(uint32_t*)&OhH[base + (size_t)r0 * DIMD + col] = pkhf(o00, o01);
        *(uint32_t*)&OhH[base + (size_t)r1 * DIMD + col] = pkhf(o10, o11);
    }
}

// ================================================================================
extern "C" void kernel_launch(void* const* d_in, const int* in_sizes, int n_in,
                              void* d_out, int out_size)
{
    const float* Q  = (const float*)d_in[0];
    const float* K  = (const float*)d_in[1];
    const float* Wq = (const float*)d_in[2];
    const float* bq = (const float*)d_in[3];
    const float* Wk = (const float*)d_in[4];
    const float* bk = (const float*)d_in[5];
    const float* Wv = (const float*)d_in[6];
    const float* bv = (const float*)d_in[7];
    const float* Wo = (const float*)d_in[8];
    const float* bo = (const float*)d_in[9];
    float* out = (float*)d_out;

    float *Qp, *Oh;
    __half *Qh, *Kh, *Vh, *OhH, *Xq, *Xk, *WqH, *WkH, *WvH, *WoH;
    cudaGetSymbolAddress((void**)&Qp,  g_Qp);
    cudaGetSymbolAddress((void**)&Oh,  g_Oh);
    cudaGetSymbolAddress((void**)&Qh,  g_Qh);
    cudaGetSymbolAddress((void**)&Kh,  g_Kh);
    cudaGetSymbolAddress((void**)&Vh,  g_Vh);
    cudaGetSymbolAddress((void**)&OhH, g_OhH);
    cudaGetSymbolAddress((void**)&Xq,  g_Xq);
    cudaGetSymbolAddress((void**)&Xk,  g_Xk);
    cudaGetSymbolAddress((void**)&WqH, g_Wq);
    cudaGetSymbolAddress((void**)&WkH, g_Wk);
    cudaGetSymbolAddress((void**)&WvH, g_Wv);
    cudaGetSymbolAddress((void**)&WoH, g_Wo);

    cudaFuncSetAttribute(attn_mma,
                         cudaFuncAttributeMaxDynamicSharedMemorySize, ATT_SMEM);
    cudaFuncSetAttribute(gemm_h<0>,
                         cudaFuncAttributeMaxDynamicSharedMemorySize, GEMM_SMEM);
    cudaFuncSetAttribute(gemm_h<1>,
                         cudaFuncAttributeMaxDynamicSharedMemorySize, GEMM_SMEM);
    cudaFuncSetAttribute(gemm_h<2>,
                         cudaFuncAttributeMaxDynamicSharedMemorySize, GEMM_SMEM);

    // ---- pre-convert inputs + weights to fp16 (value-identical to in-loop cvt) ----
    const int nX = TT * DIMD, nW = DIMD * DIMD;
    f2h_kernel<<<nX / (256 * 8), 256>>>(Q,  Xq,  nX);
    f2h_kernel<<<nX / (256 * 8), 256>>>(K,  Xk,  nX);
    f2h_kernel<<<nW / (256 * 8), 256>>>(Wq, WqH, nW);
    f2h_kernel<<<nW / (256 * 8), 256>>>(Wk, WkH, nW);
    f2h_kernel<<<nW / (256 * 8), 256>>>(Wv, WvH, nW);
    f2h_kernel<<<nW / (256 * 8), 256>>>(Wo, WoH, nW);

    dim3 gg(8, 64);
    gemm_h<1><<<gg, 256, GEMM_SMEM>>>(Xq,  WqH, bq, nullptr, Qp, Qh);
    gemm_h<0><<<gg, 256, GEMM_SMEM>>>(Xk,  WkH, bk, nullptr, nullptr, Kh);
    gemm_h<0><<<gg, 256, GEMM_SMEM>>>(Xk,  WvH, bv, nullptr, nullptr, Vh);
    attn_mma<<<dim3(16, 64), 256, ATT_SMEM>>>(Qh, Kh, Vh, Qp, Oh, OhH);
    gemm_h<2><<<gg, 256, GEMM_SMEM>>>(OhH, WoH, bo, Oh, out, nullptr);
}

// round 13
// speedup vs baseline: 1.1290x; 1.0866x over previous
#include <cuda_runtime.h>
#include <cuda_fp16.h>
#include <cstdint>
#include <cstddef>

#define DIMD   1024
#define TT     8192     // B*N = B*M rows
#define HD     64       // head dim
#define SEQ    2048

// ---------------- scratch ----------------
__device__ float  g_Qp [TT * DIMD];   // fp32 Q projection (residual)
__device__ float  g_Oh [TT * DIMD];   // fp32 attention out (residual for final gemm)
__device__ __half g_Qh [TT * DIMD];
__device__ __half g_Kh [TT * DIMD];
__device__ __half g_Vh [TT * DIMD];
__device__ __half g_OhH[TT * DIMD];

// =========================== helpers =================================
__device__ __forceinline__ uint32_t smem_u32(const void* p) {
    uint32_t a;
    asm("{ .reg .u64 t; cvta.to.shared.u64 t, %1; cvt.u32.u64 %0, t; }"
        : "=r"(a) : "l"(p));
    return a;
}

#define LDSM_X4(R0, R1, R2, R3, addr) \
    asm volatile("ldmatrix.sync.aligned.m8n8.x4.shared.b16 {%0,%1,%2,%3}, [%4];" \
                 : "=r"(R0), "=r"(R1), "=r"(R2), "=r"(R3) : "r"(addr))

#define LDSM_X4_T(R0, R1, R2, R3, addr) \
    asm volatile("ldmatrix.sync.aligned.m8n8.x4.trans.shared.b16 {%0,%1,%2,%3}, [%4];" \
                 : "=r"(R0), "=r"(R1), "=r"(R2), "=r"(R3) : "r"(addr))

#define MMA_F16(c, a, b0, b1) \
    asm volatile("mma.sync.aligned.m16n8k16.row.col.f32.f16.f16.f32 " \
                 "{%0,%1,%2,%3}, {%4,%5,%6,%7}, {%8,%9}, {%0,%1,%2,%3};" \
                 : "+f"((c)[0]), "+f"((c)[1]), "+f"((c)[2]), "+f"((c)[3]) \
                 : "r"((a)[0]), "r"((a)[1]), "r"((a)[2]), "r"((a)[3]), \
                   "r"(b0), "r"(b1))

__device__ __forceinline__ uint32_t pkhf(float lo, float hi) {
    uint32_t d;
    asm("cvt.rn.f16x2.f32 %0, %1, %2;" : "=r"(d) : "f"(hi), "f"(lo));
    return d;
}
__device__ __forceinline__ void cvt8h(const float* f, uint32_t* o) {
    #pragma unroll
    for (int i = 0; i < 4; i++) o[i] = pkhf(f[2 * i], f[2 * i + 1]);
}

// swizzled smem address: 128B rows, 8 chunks of 16B, chunk c XOR (r&7)
__device__ __forceinline__ uint32_t sw_addr(uint32_t base, int r, int c) {
    return base + (uint32_t)(r * 128) + (uint32_t)(((c ^ (r & 7)) & 7) << 4);
}

__device__ __forceinline__ void st16(uint32_t a, uint4 v) {
    asm volatile("st.shared.v4.b32 [%0], {%1,%2,%3,%4};"
                 :: "r"(a), "r"(v.x), "r"(v.y), "r"(v.z), "r"(v.w));
}

// ================================================================================
// Projection GEMM (R9-proven): C = X[8192,1024] @ W^T + bias -> fp16 CH
// (and fp32 C32 if W32). In-loop fp32->fp16 conversion staging.
// 128x128 tile, BK=32, 256 threads (8 warps, 2m x 4n), warp tile 64x32.
// ================================================================================
#define GEMM_SMEM (2 * 32768)

template <int W32>
__global__ void __launch_bounds__(256)
gemm_proj(const float* __restrict__ X, const float* __restrict__ W,
          const float* __restrict__ bias, float* __restrict__ C32,
          __half* __restrict__ CH)
{
    extern __shared__ char sm[];
    const uint32_t sb = smem_u32(sm);

    const int t    = threadIdx.x;
    const int w    = t >> 5;
    const int lane = t & 31;
    const int wm   = w >> 2;
    const int wn   = w & 3;
    const int bn   = blockIdx.x;
    const int bm   = blockIdx.y;

    float acc[4][4][4];
    #pragma unroll
    for (int mi = 0; mi < 4; mi++)
        #pragma unroll
        for (int ni = 0; ni < 4; ni++)
            #pragma unroll
            for (int q = 0; q < 4; q++) acc[mi][ni][q] = 0.0f;

    float stA[2][8], stB[2][8];
    #pragma unroll
    for (int s = 0; s < 2; s++) {
        int idx = t + 256 * s;
        int r = idx >> 2, seg = idx & 3;
        const float* pA = X + (size_t)(bm * 128 + r) * DIMD + seg * 8;
        const float* pB = W + (size_t)(bn * 128 + r) * DIMD + seg * 8;
        *(float4*)&stA[s][0] = *(const float4*)(pA);
        *(float4*)&stA[s][4] = *(const float4*)(pA + 4);
        *(float4*)&stB[s][0] = *(const float4*)(pB);
        *(float4*)&stB[s][4] = *(const float4*)(pB + 4);
    }

    const int rin = lane & 15;
    const int hb  = lane >> 4;

    for (int ch = 0; ch < 32; ch++) {
        const uint32_t Ab = sb + (uint32_t)(ch & 1) * 32768u;
        const uint32_t Bb = Ab + 16384u;

        #pragma unroll
        for (int s = 0; s < 2; s++) {
            int idx = t + 256 * s;
            int r = idx >> 2, seg = idx & 3;
            uint32_t h[4];
            cvt8h(stA[s], h);
            st16(sw_addr(Ab, r, seg), make_uint4(h[0], h[1], h[2], h[3]));
            cvt8h(stB[s], h);
            st16(sw_addr(Bb, r, seg), make_uint4(h[0], h[1], h[2], h[3]));
        }
        __syncthreads();

        if (ch + 1 < 32) {
            const int k0 = (ch + 1) * 32;
            #pragma unroll
            for (int s = 0; s < 2; s++) {
                int idx = t + 256 * s;
                int r = idx >> 2, seg = idx & 3;
                const float* pA = X + (size_t)(bm * 128 + r) * DIMD + k0 + seg * 8;
                const float* pB = W + (size_t)(bn * 128 + r) * DIMD + k0 + seg * 8;
                *(float4*)&stA[s][0] = *(const float4*)(pA);
                *(float4*)&stA[s][4] = *(const float4*)(pA + 4);
                *(float4*)&stB[s][0] = *(const float4*)(pB);
                *(float4*)&stB[s][4] = *(const float4*)(pB + 4);
            }
        }

        #pragma unroll
        for (int ks = 0; ks < 2; ks++) {
            const int chi = ks * 2 + hb;
            uint32_t afr[4][4];
            #pragma unroll
            for (int mi = 0; mi < 4; mi++)
                LDSM_X4(afr[mi][0], afr[mi][1], afr[mi][2], afr[mi][3],
                        sw_addr(Ab, wm * 64 + mi * 16 + rin, chi));
            uint32_t bh[2][4];
            #pragma unroll
            for (int pi = 0; pi < 2; pi++)
                LDSM_X4(bh[pi][0], bh[pi][1], bh[pi][2], bh[pi][3],
                        sw_addr(Bb, wn * 32 + pi * 16 + rin, chi));
            #pragma unroll
            for (int mi = 0; mi < 4; mi++)
                #pragma unroll
                for (int ni = 0; ni < 4; ni++)
                    MMA_F16(acc[mi][ni], afr[mi],
                            bh[ni >> 1][ni & 1], bh[ni >> 1][(ni & 1) + 2]);
        }
        __syncthreads();
    }

    const int rbase = bm * 128 + wm * 64;
    const int cbase = bn * 128 + wn * 32;
    float bb[4][2];
    #pragma unroll
    for (int ni = 0; ni < 4; ni++) {
        int c0 = cbase + ni * 8 + (lane & 3) * 2;
        bb[ni][0] = bias[c0];
        bb[ni][1] = bias[c0 + 1];
    }

    #pragma unroll
    for (int mi = 0; mi < 4; mi++) {
        #pragma unroll
        for (int ni = 0; ni < 4; ni++) {
            int r0 = rbase + mi * 16 + (lane >> 2);
            int c0 = cbase + ni * 8 + (lane & 3) * 2;
            float o0 = acc[mi][ni][0] + bb[ni][0];
            float o1 = acc[mi][ni][1] + bb[ni][1];
            float o2 = acc[mi][ni][2] + bb[ni][0];
            float o3 = acc[mi][ni][3] + bb[ni][1];
            *(uint32_t*)&CH[(size_t)r0 * DIMD + c0]       = pkhf(o0, o1);
            *(uint32_t*)&CH[(size_t)(r0 + 8) * DIMD + c0] = pkhf(o2, o3);
            if (W32) {
                *(float2*)&C32[(size_t)r0 * DIMD + c0]       = make_float2(o0, o1);
                *(float2*)&C32[(size_t)(r0 + 8) * DIMD + c0] = make_float2(o2, o3);
            }
        }
    }
}

// ================================================================================
// Output GEMM (R9-proven): out = R + relu(Xh @ W^T + bias), Xh fp16, R/out fp32.
// ================================================================================
__global__ void __launch_bounds__(256)
gemm_out(const __half* __restrict__ X, const float* __restrict__ W,
         const float* __restrict__ bias, const float* __restrict__ R,
         float* __restrict__ C)
{
    extern __shared__ char sm[];
    const uint32_t sb = smem_u32(sm);

    const int t    = threadIdx.x;
    const int w    = t >> 5;
    const int lane = t & 31;
    const int wm   = w >> 2;
    const int wn   = w & 3;
    const int bn   = blockIdx.x;
    const int bm   = blockIdx.y;

    float acc[4][4][4];
    #pragma unroll
    for (int mi = 0; mi < 4; mi++)
        #pragma unroll
        for (int ni = 0; ni < 4; ni++)
            #pragma unroll
            for (int q = 0; q < 4; q++) acc[mi][ni][q] = 0.0f;

    uint4 stA[2];
    float stB[2][8];
    #pragma unroll
    for (int s = 0; s < 2; s++) {
        int idx = t + 256 * s;
        int r = idx >> 2, seg = idx & 3;
        stA[s] = *(const uint4*)&X[(size_t)(bm * 128 + r) * DIMD + seg * 8];
        const float* pB = W + (size_t)(bn * 128 + r) * DIMD + seg * 8;
        *(float4*)&stB[s][0] = *(const float4*)(pB);
        *(float4*)&stB[s][4] = *(const float4*)(pB + 4);
    }

    const int rin = lane & 15;
    const int hb  = lane >> 4;

    for (int ch = 0; ch < 32; ch++) {
        const uint32_t Ab = sb + (uint32_t)(ch & 1) * 32768u;
        const uint32_t Bb = Ab + 16384u;

        #pragma unroll
        for (int s = 0; s < 2; s++) {
            int idx = t + 256 * s;
            int r = idx >> 2, seg = idx & 3;
            st16(sw_addr(Ab, r, seg), stA[s]);
            uint32_t h[4];
            cvt8h(stB[s], h);
            st16(sw_addr(Bb, r, seg), make_uint4(h[0], h[1], h[2], h[3]));
        }
        __syncthreads();

        if (ch + 1 < 32) {
            const int k0 = (ch + 1) * 32;
            #pragma unroll
            for (int s = 0; s < 2; s++) {
                int idx = t + 256 * s;
                int r = idx >> 2, seg = idx & 3;
                stA[s] = *(const uint4*)&X[(size_t)(bm * 128 + r) * DIMD + k0 + seg * 8];
                const float* pB = W + (size_t)(bn * 128 + r) * DIMD + k0 + seg * 8;
                *(float4*)&stB[s][0] = *(const float4*)(pB);
                *(float4*)&stB[s][4] = *(const float4*)(pB + 4);
            }
        }

        #pragma unroll
        for (int ks = 0; ks < 2; ks++) {
            const int chi = ks * 2 + hb;
            uint32_t afr[4][4];
            #pragma unroll
            for (int mi = 0; mi < 4; mi++)
                LDSM_X4(afr[mi][0], afr[mi][1], afr[mi][2], afr[mi][3],
                        sw_addr(Ab, wm * 64 + mi * 16 + rin, chi));
            uint32_t bh[2][4];
            #pragma unroll
            for (int pi = 0; pi < 2; pi++)
                LDSM_X4(bh[pi][0], bh[pi][1], bh[pi][2], bh[pi][3],
                        sw_addr(Bb, wn * 32 + pi * 16 + rin, chi));
            #pragma unroll
            for (int mi = 0; mi < 4; mi++)
                #pragma unroll
                for (int ni = 0; ni < 4; ni++)
                    MMA_F16(acc[mi][ni], afr[mi],
                            bh[ni >> 1][ni & 1], bh[ni >> 1][(ni & 1) + 2]);
        }
        __syncthreads();
    }

    const int rbase = bm * 128 + wm * 64;
    const int cbase = bn * 128 + wn * 32;
    float bb[4][2];
    #pragma unroll
    for (int ni = 0; ni < 4; ni++) {
        int c0 = cbase + ni * 8 + (lane & 3) * 2;
        bb[ni][0] = bias[c0];
        bb[ni][1] = bias[c0 + 1];
    }

    #pragma unroll
    for (int mi = 0; mi < 4; mi++) {
        #pragma unroll
        for (int ni = 0; ni < 4; ni++) {
            int r0 = rbase + mi * 16 + (lane >> 2);
            int c0 = cbase + ni * 8 + (lane & 3) * 2;
            float2 ra = *(const float2*)&R[(size_t)r0 * DIMD + c0];
            float2 rb = *(const float2*)&R[(size_t)(r0 + 8) * DIMD + c0];
            float o0 = fmaxf(acc[mi][ni][0] + bb[ni][0], 0.0f) + ra.x;
            float o1 = fmaxf(acc[mi][ni][1] + bb[ni][1], 0.0f) + ra.y;
            float o2 = fmaxf(acc[mi][ni][2] + bb[ni][0], 0.0f) + rb.x;
            float o3 = fmaxf(acc[mi][ni][3] + bb[ni][1], 0.0f) + rb.y;
            *(float2*)&C[(size_t)r0 * DIMD + c0]       = make_float2(o0, o1);
            *(float2*)&C[(size_t)(r0 + 8) * DIMD + c0] = make_float2(o2, o3);
        }
    }
}

// ================================================================================
// Tensor-core flash attention per (b,h): Br=128, Bc=64, d=64.
// 4 warps (128 threads), 32 Q-rows per warp (2 m-tiles) -> halves LDSM traffic.
// Keys processed in two 32-wide halves to bound live registers (sacc 32 regs).
// fp16 inputs, fp32 accum. No max subtraction (scores provably tiny).
// ================================================================================
#define ATT_SMEM (16384 + 8192 + 8192)

__global__ void __launch_bounds__(128, 2)
attn_mma(const __half* __restrict__ Qh, const __half* __restrict__ Kh,
         const __half* __restrict__ Vh, const float* __restrict__ Qp,
         float* __restrict__ Oh, __half* __restrict__ OhH)
{
    extern __shared__ char smatt[];
    const uint32_t sb = smem_u32(smatt);
    const uint32_t Qs = sb;
    const uint32_t Ks = sb + 16384;
    const uint32_t Vs = sb + 24576;

    const int t    = threadIdx.x;
    const int w    = t >> 5;        // 0..3
    const int lane = t & 31;
    const int rin  = lane & 15;
    const int hb   = lane >> 4;
    const int bh   = blockIdx.y;
    const int b    = bh >> 4;
    const int h    = bh & 15;
    const int n0   = blockIdx.x * 128;

    const size_t base = (size_t)b * SEQ * DIMD + (size_t)h * HD;

    // ---- stage Q tile: 128 rows x 64 d fp16 (1 row/thread, all 8 chunks) ----
    {
        const __half* src = Qh + base + (size_t)(n0 + t) * DIMD;
        #pragma unroll
        for (int g = 0; g < 8; g++)
            st16(sw_addr(Qs, t, g), *(const uint4*)(src + g * 8));
    }
    __syncthreads();

    // ---- load Q fragments once: 2 m-tiles x 4 k-steps ----
    uint32_t qf[2][4][4];
    #pragma unroll
    for (int mi = 0; mi < 2; mi++)
        #pragma unroll
        for (int ks = 0; ks < 4; ks++)
            LDSM_X4(qf[mi][ks][0], qf[mi][ks][1], qf[mi][ks][2], qf[mi][ks][3],
                    sw_addr(Qs, w * 32 + mi * 16 + rin, 2 * ks + hb));

    float oacc[2][8][4];
    #pragma unroll
    for (int mi = 0; mi < 2; mi++)
        #pragma unroll
        for (int j = 0; j < 8; j++)
            #pragma unroll
            for (int q = 0; q < 4; q++) oacc[mi][j][q] = 0.0f;
    float lr[2][2] = {{0.0f, 0.0f}, {0.0f, 0.0f}};

    // K/V staging: 64 rows x 8 chunks = 512 chunks per tile; 4 chunks/thread.
    const int srow = t >> 1;          // 0..63
    const int scol = (t & 1) * 4;     // chunks scol..scol+3
    uint4 kpre[4], vpre[4];
    {
        const __half* kp = Kh + base + (size_t)srow * DIMD + scol * 8;
        const __half* vp = Vh + base + (size_t)srow * DIMD + scol * 8;
        #pragma unroll
        for (int g = 0; g < 4; g++) {
            kpre[g] = *(const uint4*)(kp + g * 8);
            vpre[g] = *(const uint4*)(vp + g * 8);
        }
    }

    for (int m0 = 0; m0 < SEQ; m0 += 64) {
        #pragma unroll
        for (int g = 0; g < 4; g++) {
            st16(sw_addr(Ks, srow, scol + g), kpre[g]);
            st16(sw_addr(Vs, srow, scol + g), vpre[g]);
        }
        __syncthreads();

        if (m0 + 64 < SEQ) {
            const __half* kp = Kh + base + (size_t)(m0 + 64 + srow) * DIMD + scol * 8;
            const __half* vp = Vh + base + (size_t)(m0 + 64 + srow) * DIMD + scol * 8;
            #pragma unroll
            for (int g = 0; g < 4; g++) {
                kpre[g] = *(const uint4*)(kp + g * 8);
                vpre[g] = *(const uint4*)(vp + g * 8);
            }
        }

        // process keys in two 32-wide halves (bounds live sacc registers)
        #pragma unroll
        for (int kh = 0; kh < 2; kh++) {
            // ---- S = Q K^T : 32 rows x 32 keys per warp ----
            float sacc[2][4][4];
            #pragma unroll
            for (int mi = 0; mi < 2; mi++)
                #pragma unroll
                for (int j = 0; j < 4; j++)
                    #pragma unroll
                    for (int q = 0; q < 4; q++) sacc[mi][j][q] = 0.0f;

            #pragma unroll
            for (int ks = 0; ks < 4; ks++) {
                uint32_t kb[2][4];
                #pragma unroll
                for (int pi = 0; pi < 2; pi++)
                    LDSM_X4(kb[pi][0], kb[pi][1], kb[pi][2], kb[pi][3],
                            sw_addr(Ks, kh * 32 + pi * 16 + rin, 2 * ks + hb));
                #pragma unroll
                for (int mi = 0; mi < 2; mi++)
                    #pragma unroll
                    for (int pi = 0; pi < 2; pi++) {
                        MMA_F16(sacc[mi][2 * pi],     qf[mi][ks], kb[pi][0], kb[pi][2]);
                        MMA_F16(sacc[mi][2 * pi + 1], qf[mi][ks], kb[pi][1], kb[pi][3]);
                    }
            }

            // ---- p = exp(s/32); accumulate l; pack P ----
            uint32_t pf[2][4][2];
            #pragma unroll
            for (int mi = 0; mi < 2; mi++)
                #pragma unroll
                for (int j = 0; j < 4; j++) {
                    float p0 = __expf(sacc[mi][j][0] * 0.03125f);
                    float p1 = __expf(sacc[mi][j][1] * 0.03125f);
                    float p2 = __expf(sacc[mi][j][2] * 0.03125f);
                    float p3 = __expf(sacc[mi][j][3] * 0.03125f);
                    lr[mi][0] += p0 + p1;
                    lr[mi][1] += p2 + p3;
                    pf[mi][j][0] = pkhf(p0, p1);
                    pf[mi][j][1] = pkhf(p2, p3);
                }

            // ---- O += P @ V over this key half ----
            #pragma unroll
            for (int ks2 = 0; ks2 < 2; ks2++) {
                uint32_t pa[2][4];
                #pragma unroll
                for (int mi = 0; mi < 2; mi++) {
                    pa[mi][0] = pf[mi][2 * ks2][0];     pa[mi][1] = pf[mi][2 * ks2][1];
                    pa[mi][2] = pf[mi][2 * ks2 + 1][0]; pa[mi][3] = pf[mi][2 * ks2 + 1][1];
                }
                #pragma unroll
                for (int pi = 0; pi < 4; pi++) {
                    uint32_t vb0, vb1, vb2, vb3;
                    LDSM_X4_T(vb0, vb1, vb2, vb3,
                              sw_addr(Vs, kh * 32 + ks2 * 16 + rin, 2 * pi + hb));
                    #pragma unroll
                    for (int mi = 0; mi < 2; mi++) {
                        MMA_F16(oacc[mi][2 * pi],     pa[mi], vb0, vb1);
                        MMA_F16(oacc[mi][2 * pi + 1], pa[mi], vb2, vb3);
                    }
                }
            }
        }
        __syncthreads();
    }

    // ---- finalize: quad-reduce l, O = acc/l + Qp (fp32 residual) ----
    #pragma unroll
    for (int mi = 0; mi < 2; mi++) {
        lr[mi][0] += __shfl_xor_sync(0xffffffffu, lr[mi][0], 1);
        lr[mi][0] += __shfl_xor_sync(0xffffffffu, lr[mi][0], 2);
        lr[mi][1] += __shfl_xor_sync(0xffffffffu, lr[mi][1], 1);
        lr[mi][1] += __shfl_xor_sync(0xffffffffu, lr[mi][1], 2);
        const float inv0 = 1.0f / lr[mi][0];
        const float inv1 = 1.0f / lr[mi][1];

        const int r0 = n0 + w * 32 + mi * 16 + (lane >> 2);
        const int r1 = r0 + 8;
        #pragma unroll
        for (int j = 0; j < 8; j++) {
            const int col = j * 8 + (lane & 3) * 2;
            float2 q0 = *(const float2*)&Qp[base + (size_t)r0 * DIMD + col];
            float2 q1 = *(const float2*)&Qp[base + (size_t)r1 * DIMD + col];
            float o00 = oacc[mi][j][0] * inv0 + q0.x;
            float o01 = oacc[mi][j][1] * inv0 + q0.y;
            float o10 = oacc[mi][j][2] * inv1 + q1.x;
            float o11 = oacc[mi][j][3] * inv1 + q1.y;
            *(float2*)&Oh[base + (size_t)r0 * DIMD + col] = make_float2(o00, o01);
            *(float2*)&Oh[base + (size_t)r1 * DIMD + col] = make_float2(o10, o11);
            *(uint32_t*)&OhH[base + (size_t)r0 * DIMD + col] = pkhf(o00, o01);
            *(uint32_t*)&OhH[base + (size_t)r1 * DIMD + col] = pkhf(o10, o11);
        }
    }
}

// ================================================================================
extern "C" void kernel_launch(void* const* d_in, const int* in_sizes, int n_in,
                              void* d_out, int out_size)
{
    const float* Q  = (const float*)d_in[0];
    const float* K  = (const float*)d_in[1];
    const float* Wq = (const float*)d_in[2];
    const float* bq = (const float*)d_in[3];
    const float* Wk = (const float*)d_in[4];
    const float* bk = (const float*)d_in[5];
    const float* Wv = (const float*)d_in[6];
    const float* bv = (const float*)d_in[7];
    const float* Wo = (const float*)d_in[8];
    const float* bo = (const float*)d_in[9];
    float* out = (float*)d_out;

    float *Qp, *Oh;
    __half *Qh, *Kh, *Vh, *OhH;
    cudaGetSymbolAddress((void**)&Qp,  g_Qp);
    cudaGetSymbolAddress((void**)&Oh,  g_Oh);
    cudaGetSymbolAddress((void**)&Qh,  g_Qh);
    cudaGetSymbolAddress((void**)&Kh,  g_Kh);
    cudaGetSymbolAddress((void**)&Vh,  g_Vh);
    cudaGetSymbolAddress((void**)&OhH, g_OhH);

    cudaFuncSetAttribute(attn_mma,
                         cudaFuncAttributeMaxDynamicSharedMemorySize, ATT_SMEM);
    cudaFuncSetAttribute(gemm_proj<0>,
                         cudaFuncAttributeMaxDynamicSharedMemorySize, GEMM_SMEM);
    cudaFuncSetAttribute(gemm_proj<1>,
                         cudaFuncAttributeMaxDynamicSharedMemorySize, GEMM_SMEM);
    cudaFuncSetAttribute(gemm_out,
                         cudaFuncAttributeMaxDynamicSharedMemorySize, GEMM_SMEM);

    dim3 gg(8, 64);
    gemm_proj<1><<<gg, 256, GEMM_SMEM>>>(Q, Wq, bq, Qp, Qh);
    gemm_proj<0><<<gg, 256, GEMM_SMEM>>>(K, Wk, bk, nullptr, Kh);
    gemm_proj<0><<<gg, 256, GEMM_SMEM>>>(K, Wv, bv, nullptr, Vh);
    attn_mma<<<dim3(16, 64), 128, ATT_SMEM>>>(Qh, Kh, Vh, Qp, Oh, OhH);
    gemm_out<<<gg, 256, GEMM_SMEM>>>(OhH, Wo, bo, Oh, out);
}